// round 2
// baseline (speedup 1.0000x reference)
#include <cuda_runtime.h>

#define NBATCH 8
#define SEQ 2048
#define DIM 128
#define NPAIR 2
#define LCHUNKS 4
#define LCHUNK (SEQ / LCHUNKS)

// Scratch (device globals -- no allocation allowed in kernel_launch)
__device__ float g_proj[(size_t)NPAIR * NBATCH * SEQ * DIM];       // 16 MB
__device__ float g_att[(size_t)NPAIR * NBATCH * SEQ * SEQ];        // 268 MB
__device__ float g_rowmax[NPAIR * NBATCH * SEQ];
__device__ float g_rowinv[NPAIR * NBATCH * SEQ];
__device__ float g_diag[NPAIR * NBATCH * SEQ];
__device__ float g_part[LCHUNKS * NPAIR * NBATCH * SEQ];
__device__ float g_score[NPAIR * NBATCH * SEQ];
__device__ float g_theta[NPAIR * NBATCH];

// ---------------------------------------------------------------------------
// Projection: P = X @ W^T + b   for both x_t (p=0) and x_f (p=1)
// grid (128, 2), block 256. 128x128 tile, K=128 in chunks of 32.
// ---------------------------------------------------------------------------
__global__ __launch_bounds__(256) void proj_kernel(
    const float* __restrict__ xt, const float* __restrict__ xf,
    const float* __restrict__ W, const float* __restrict__ bias)
{
    __shared__ float As[128][33];
    __shared__ float Bs[128][33];
    const int p = blockIdx.y;
    const float* __restrict__ X = (p == 0) ? xt : xf;
    const int rbase = blockIdx.x * 128;
    const int tid = threadIdx.x;
    const int tx = tid & 15, ty = tid >> 4;
    const int r0 = ty * 8, c0 = tx * 8;
    float acc[8][8];
#pragma unroll
    for (int i = 0; i < 8; i++)
#pragma unroll
        for (int j = 0; j < 8; j++) acc[i][j] = 0.f;

    for (int kk0 = 0; kk0 < DIM; kk0 += 32) {
#pragma unroll
        for (int it = 0; it < 4; it++) {
            int idx4 = it * 256 + tid;
            int r = idx4 >> 3;
            int k4 = (idx4 & 7) * 4;
            float4 v = *(const float4*)(X + (size_t)(rbase + r) * DIM + kk0 + k4);
            As[r][k4 + 0] = v.x; As[r][k4 + 1] = v.y; As[r][k4 + 2] = v.z; As[r][k4 + 3] = v.w;
            float4 w = *(const float4*)(W + (size_t)r * DIM + kk0 + k4);
            Bs[r][k4 + 0] = w.x; Bs[r][k4 + 1] = w.y; Bs[r][k4 + 2] = w.z; Bs[r][k4 + 3] = w.w;
        }
        __syncthreads();
#pragma unroll
        for (int k = 0; k < 32; k++) {
            float a[8], b[8];
#pragma unroll
            for (int j = 0; j < 8; j++) { a[j] = As[r0 + j][k]; b[j] = Bs[c0 + j][k]; }
#pragma unroll
            for (int i = 0; i < 8; i++)
#pragma unroll
                for (int j = 0; j < 8; j++)
                    acc[i][j] = fmaf(a[i], b[j], acc[i][j]);
        }
        __syncthreads();
    }
    float bv[8];
#pragma unroll
    for (int j = 0; j < 8; j++) bv[j] = bias[c0 + j];
    float* out = g_proj + ((size_t)p * NBATCH * SEQ + rbase) * DIM;
#pragma unroll
    for (int i = 0; i < 8; i++) {
        float4 v0, v1;
        v0.x = acc[i][0] + bv[0]; v0.y = acc[i][1] + bv[1];
        v0.z = acc[i][2] + bv[2]; v0.w = acc[i][3] + bv[3];
        v1.x = acc[i][4] + bv[4]; v1.y = acc[i][5] + bv[5];
        v1.z = acc[i][6] + bv[6]; v1.w = acc[i][7] + bv[7];
        float* dst = out + (size_t)(r0 + i) * DIM + c0;
        *(float4*)dst = v0;
        *(float4*)(dst + 4) = v1;
    }
}

// ---------------------------------------------------------------------------
// Attention logits: att = scale * P P^T (symmetric: upper-tri tiles, mirrored)
// grid (136, 8, 2), block 256.
// ---------------------------------------------------------------------------
__global__ __launch_bounds__(256) void att_kernel()
{
    __shared__ float As[128][33];
    __shared__ float Bs[128][33];
    int t = blockIdx.x;
    int ti = 0;
    while (t >= 16 - ti) { t -= 16 - ti; ti++; }
    const int tj = ti + t;
    const int n = blockIdx.y, p = blockIdx.z;
    const float* __restrict__ P = g_proj + ((size_t)p * NBATCH + n) * SEQ * DIM;
    float* __restrict__ att = g_att + ((size_t)p * NBATCH + n) * SEQ * SEQ;
    const int tid = threadIdx.x;
    const int tx = tid & 15, ty = tid >> 4;
    const int r0 = ty * 8, c0 = tx * 8;
    const float* __restrict__ Arow = P + (size_t)ti * 128 * DIM;
    const float* __restrict__ Brow = P + (size_t)tj * 128 * DIM;
    float acc[8][8];
#pragma unroll
    for (int i = 0; i < 8; i++)
#pragma unroll
        for (int j = 0; j < 8; j++) acc[i][j] = 0.f;

    for (int kk0 = 0; kk0 < DIM; kk0 += 32) {
#pragma unroll
        for (int it = 0; it < 4; it++) {
            int idx4 = it * 256 + tid;
            int r = idx4 >> 3;
            int k4 = (idx4 & 7) * 4;
            float4 v = *(const float4*)(Arow + (size_t)r * DIM + kk0 + k4);
            As[r][k4 + 0] = v.x; As[r][k4 + 1] = v.y; As[r][k4 + 2] = v.z; As[r][k4 + 3] = v.w;
            float4 w = *(const float4*)(Brow + (size_t)r * DIM + kk0 + k4);
            Bs[r][k4 + 0] = w.x; Bs[r][k4 + 1] = w.y; Bs[r][k4 + 2] = w.z; Bs[r][k4 + 3] = w.w;
        }
        __syncthreads();
#pragma unroll
        for (int k = 0; k < 32; k++) {
            float a[8], b[8];
#pragma unroll
            for (int j = 0; j < 8; j++) { a[j] = As[r0 + j][k]; b[j] = Bs[c0 + j][k]; }
#pragma unroll
            for (int i = 0; i < 8; i++)
#pragma unroll
                for (int j = 0; j < 8; j++)
                    acc[i][j] = fmaf(a[i], b[j], acc[i][j]);
        }
        __syncthreads();
    }
    const float scale = 0.088388347648318447f;  // 1/sqrt(128)
#pragma unroll
    for (int i = 0; i < 8; i++)
#pragma unroll
        for (int j = 0; j < 8; j++) acc[i][j] *= scale;

    // normal tile write
#pragma unroll
    for (int i = 0; i < 8; i++) {
        float4 v0, v1;
        v0.x = acc[i][0]; v0.y = acc[i][1]; v0.z = acc[i][2]; v0.w = acc[i][3];
        v1.x = acc[i][4]; v1.y = acc[i][5]; v1.z = acc[i][6]; v1.w = acc[i][7];
        float* dst = att + (size_t)(ti * 128 + r0 + i) * SEQ + tj * 128 + c0;
        *(float4*)dst = v0;
        *(float4*)(dst + 4) = v1;
    }
    // mirrored (transposed) tile write
    if (ti != tj) {
#pragma unroll
        for (int j = 0; j < 8; j++) {
            float4 v0, v1;
            v0.x = acc[0][j]; v0.y = acc[1][j]; v0.z = acc[2][j]; v0.w = acc[3][j];
            v1.x = acc[4][j]; v1.y = acc[5][j]; v1.z = acc[6][j]; v1.w = acc[7][j];
            float* dst = att + (size_t)(tj * 128 + c0 + j) * SEQ + ti * 128 + r0;
            *(float4*)dst = v0;
            *(float4*)(dst + 4) = v1;
        }
    }
}

// ---------------------------------------------------------------------------
// Row statistics: max, 1/sum(exp(x-max)), and the diagonal softmax value.
// grid 2*8*2048 blocks, block 256 (8 elems/thread).
// ---------------------------------------------------------------------------
__global__ __launch_bounds__(256) void rowstat_kernel()
{
    const int row = blockIdx.x;
    const float* __restrict__ a = g_att + (size_t)row * SEQ;
    const int tid = threadIdx.x;
    float v[8];
    float m = -3.4e38f;
#pragma unroll
    for (int i = 0; i < 8; i++) { v[i] = a[tid + i * 256]; m = fmaxf(m, v[i]); }
    __shared__ float red[256];
    red[tid] = m; __syncthreads();
    for (int s = 128; s > 0; s >>= 1) {
        if (tid < s) red[tid] = fmaxf(red[tid], red[tid + s]);
        __syncthreads();
    }
    m = red[0];
    __syncthreads();
    float sum = 0.f;
#pragma unroll
    for (int i = 0; i < 8; i++) sum += expf(v[i] - m);
    red[tid] = sum; __syncthreads();
    for (int s = 128; s > 0; s >>= 1) {
        if (tid < s) red[tid] += red[tid + s];
        __syncthreads();
    }
    if (tid == 0) {
        float inv = 1.f / red[0];
        g_rowmax[row] = m;
        g_rowinv[row] = inv;
        int l = row & (SEQ - 1);
        g_diag[row] = expf(a[l] - m) * inv;
    }
}

// ---------------------------------------------------------------------------
// Column sums of the softmax matrix, in 4 deterministic L-chunks.
// grid (8, 16, 4), block 256 (one column per thread).
// ---------------------------------------------------------------------------
__global__ __launch_bounds__(256) void colsum_kernel()
{
    const int col = blockIdx.x * 256 + threadIdx.x;
    const int pn = blockIdx.y;
    const int lc = blockIdx.z;
    const float* __restrict__ att = g_att + (size_t)pn * SEQ * SEQ;
    const float* __restrict__ rmax = g_rowmax + pn * SEQ;
    const float* __restrict__ rinv = g_rowinv + pn * SEQ;
    __shared__ float smax[256], sinv[256];
    float acc = 0.f;
    const int l0 = lc * LCHUNK;
    for (int c = 0; c < LCHUNK; c += 256) {
        __syncthreads();
        smax[threadIdx.x] = rmax[l0 + c + threadIdx.x];
        sinv[threadIdx.x] = rinv[l0 + c + threadIdx.x];
        __syncthreads();
        const float* base = att + (size_t)(l0 + c) * SEQ + col;
#pragma unroll 8
        for (int l = 0; l < 256; l++)
            acc += expf(base[(size_t)l * SEQ] - smax[l]) * sinv[l];
    }
    g_part[((size_t)lc * NPAIR * NBATCH + pn) * SEQ + col] = acc;
}

// ---------------------------------------------------------------------------
// Per (pair,batch): final score (fixed-order partial sum minus diagonal),
// bitonic sort 2048 elems, theta = k-th smallest (k=1024).
// grid 16, block 1024.
// ---------------------------------------------------------------------------
__global__ __launch_bounds__(1024) void select_kernel()
{
    const int pn = blockIdx.x;
    __shared__ float s[2048];
    const int tid = threadIdx.x;
    const int PN = NPAIR * NBATCH;
    for (int i = tid; i < SEQ; i += 1024) {
        float v = g_part[((size_t)0 * PN + pn) * SEQ + i]
                + g_part[((size_t)1 * PN + pn) * SEQ + i]
                + g_part[((size_t)2 * PN + pn) * SEQ + i]
                + g_part[((size_t)3 * PN + pn) * SEQ + i]
                - g_diag[pn * SEQ + i];
        g_score[pn * SEQ + i] = v;
        s[i] = v;
    }
    __syncthreads();
    for (int k = 2; k <= 2048; k <<= 1) {
        for (int j = k >> 1; j > 0; j >>= 1) {
            for (int idx = tid; idx < 2048; idx += 1024) {
                int ixj = idx ^ j;
                if (ixj > idx) {
                    bool up = ((idx & k) == 0);
                    float a = s[idx], b = s[ixj];
                    if ((a > b) == up) { s[idx] = b; s[ixj] = a; }
                }
            }
            __syncthreads();
        }
    }
    if (tid == 0) g_theta[pn] = s[1023];   // 1024-th smallest
}

// ---------------------------------------------------------------------------
// Output blend. mask = score <= theta (bottom-k, matching reference ties).
// mt1 = mt & ~mf  -> out_t = 0.5*(x_t + x_f) else x_t (exact). Same for f.
// grid 2048, block 256 (one float4 of both outputs per thread).
// ---------------------------------------------------------------------------
__global__ __launch_bounds__(256) void output_kernel(
    const float* __restrict__ xt, const float* __restrict__ xf, float* __restrict__ out)
{
    const int idx = blockIdx.x * 256 + threadIdx.x;  // float4 index, 524288 total
    const int nl = idx >> 5;                          // 32 float4 per D-row
    const int n = nl >> 11;
    const int l = nl & (SEQ - 1);
    const float st = g_score[n * SEQ + l];
    const float sf = g_score[(NBATCH + n) * SEQ + l];
    const bool mt = st <= g_theta[n];
    const bool mf = sf <= g_theta[NBATCH + n];
    const bool mt1 = mt && !mf;
    const bool mf1 = mf && !mt;
    const float4 vt = ((const float4*)xt)[idx];
    const float4 vf = ((const float4*)xf)[idx];
    float4 avg;
    avg.x = 0.5f * (vt.x + vf.x);
    avg.y = 0.5f * (vt.y + vf.y);
    avg.z = 0.5f * (vt.z + vf.z);
    avg.w = 0.5f * (vt.w + vf.w);
    ((float4*)out)[idx] = mt1 ? avg : vt;
    ((float4*)out)[(size_t)NBATCH * SEQ * (DIM / 4) + idx] = mf1 ? avg : vf;
}

extern "C" void kernel_launch(void* const* d_in, const int* in_sizes, int n_in,
                              void* d_out, int out_size)
{
    const float* xt = (const float*)d_in[0];
    const float* xf = (const float*)d_in[1];
    const float* W  = (const float*)d_in[2];
    const float* b  = (const float*)d_in[3];
    float* out = (float*)d_out;

    proj_kernel<<<dim3(128, 2), 256>>>(xt, xf, W, b);
    att_kernel<<<dim3(136, 8, 2), 256>>>();
    rowstat_kernel<<<NPAIR * NBATCH * SEQ, 256>>>();
    colsum_kernel<<<dim3(8, 16, 4), 256>>>();
    select_kernel<<<16, 1024>>>();
    output_kernel<<<2048, 256>>>(xt, xf, out);
}

// round 3
// speedup vs baseline: 1.0013x; 1.0013x over previous
#include <cuda_runtime.h>

#define NBATCH 8
#define SEQ 2048
#define DIM 128
#define NPAIR 2
#define LCHUNKS 4
#define LCHUNK (SEQ / LCHUNKS)

// Scratch (device globals -- no allocation allowed in kernel_launch)
__device__ float g_proj[(size_t)NPAIR * NBATCH * SEQ * DIM];       // 16 MB
__device__ float g_att[(size_t)NPAIR * NBATCH * SEQ * SEQ];        // 268 MB
__device__ float g_rowmax[NPAIR * NBATCH * SEQ];
__device__ float g_rowinv[NPAIR * NBATCH * SEQ];
__device__ float g_diag[NPAIR * NBATCH * SEQ];
__device__ float g_part[LCHUNKS * NPAIR * NBATCH * SEQ];
__device__ float g_score[NPAIR * NBATCH * SEQ];
__device__ float g_theta[NPAIR * NBATCH];

// ---------------------------------------------------------------------------
// Projection: P = X @ W^T + b   for both x_t (p=0) and x_f (p=1)
// grid (128, 2), block 256. 128x128 tile, K=128 in chunks of 32.
// ---------------------------------------------------------------------------
__global__ __launch_bounds__(256) void proj_kernel(
    const float* __restrict__ xt, const float* __restrict__ xf,
    const float* __restrict__ W, const float* __restrict__ bias)
{
    __shared__ float As[128][33];
    __shared__ float Bs[128][33];
    const int p = blockIdx.y;
    const float* __restrict__ X = (p == 0) ? xt : xf;
    const int rbase = blockIdx.x * 128;
    const int tid = threadIdx.x;
    const int tx = tid & 15, ty = tid >> 4;
    const int r0 = ty * 8, c0 = tx * 8;
    float acc[8][8];
#pragma unroll
    for (int i = 0; i < 8; i++)
#pragma unroll
        for (int j = 0; j < 8; j++) acc[i][j] = 0.f;

    for (int kk0 = 0; kk0 < DIM; kk0 += 32) {
#pragma unroll
        for (int it = 0; it < 4; it++) {
            int idx4 = it * 256 + tid;
            int r = idx4 >> 3;
            int k4 = (idx4 & 7) * 4;
            float4 v = *(const float4*)(X + (size_t)(rbase + r) * DIM + kk0 + k4);
            As[r][k4 + 0] = v.x; As[r][k4 + 1] = v.y; As[r][k4 + 2] = v.z; As[r][k4 + 3] = v.w;
            float4 w = *(const float4*)(W + (size_t)r * DIM + kk0 + k4);
            Bs[r][k4 + 0] = w.x; Bs[r][k4 + 1] = w.y; Bs[r][k4 + 2] = w.z; Bs[r][k4 + 3] = w.w;
        }
        __syncthreads();
#pragma unroll
        for (int k = 0; k < 32; k++) {
            float a[8], b[8];
#pragma unroll
            for (int j = 0; j < 8; j++) { a[j] = As[r0 + j][k]; b[j] = Bs[c0 + j][k]; }
#pragma unroll
            for (int i = 0; i < 8; i++)
#pragma unroll
                for (int j = 0; j < 8; j++)
                    acc[i][j] = fmaf(a[i], b[j], acc[i][j]);
        }
        __syncthreads();
    }
    float bv[8];
#pragma unroll
    for (int j = 0; j < 8; j++) bv[j] = bias[c0 + j];
    float* out = g_proj + ((size_t)p * NBATCH * SEQ + rbase) * DIM;
#pragma unroll
    for (int i = 0; i < 8; i++) {
        float4 v0, v1;
        v0.x = acc[i][0] + bv[0]; v0.y = acc[i][1] + bv[1];
        v0.z = acc[i][2] + bv[2]; v0.w = acc[i][3] + bv[3];
        v1.x = acc[i][4] + bv[4]; v1.y = acc[i][5] + bv[5];
        v1.z = acc[i][6] + bv[6]; v1.w = acc[i][7] + bv[7];
        float* dst = out + (size_t)(r0 + i) * DIM + c0;
        *(float4*)dst = v0;
        *(float4*)(dst + 4) = v1;
    }
}

// ---------------------------------------------------------------------------
// Attention logits: att = scale * P P^T (symmetric: upper-tri tiles, mirrored)
// grid (136, 8, 2), block 256.
// ---------------------------------------------------------------------------
__global__ __launch_bounds__(256) void att_kernel()
{
    __shared__ float As[128][33];
    __shared__ float Bs[128][33];
    int t = blockIdx.x;
    int ti = 0;
    while (t >= 16 - ti) { t -= 16 - ti; ti++; }
    const int tj = ti + t;
    const int n = blockIdx.y, p = blockIdx.z;
    const float* __restrict__ P = g_proj + ((size_t)p * NBATCH + n) * SEQ * DIM;
    float* __restrict__ att = g_att + ((size_t)p * NBATCH + n) * SEQ * SEQ;
    const int tid = threadIdx.x;
    const int tx = tid & 15, ty = tid >> 4;
    const int r0 = ty * 8, c0 = tx * 8;
    const float* __restrict__ Arow = P + (size_t)ti * 128 * DIM;
    const float* __restrict__ Brow = P + (size_t)tj * 128 * DIM;
    float acc[8][8];
#pragma unroll
    for (int i = 0; i < 8; i++)
#pragma unroll
        for (int j = 0; j < 8; j++) acc[i][j] = 0.f;

    for (int kk0 = 0; kk0 < DIM; kk0 += 32) {
#pragma unroll
        for (int it = 0; it < 4; it++) {
            int idx4 = it * 256 + tid;
            int r = idx4 >> 3;
            int k4 = (idx4 & 7) * 4;
            float4 v = *(const float4*)(Arow + (size_t)r * DIM + kk0 + k4);
            As[r][k4 + 0] = v.x; As[r][k4 + 1] = v.y; As[r][k4 + 2] = v.z; As[r][k4 + 3] = v.w;
            float4 w = *(const float4*)(Brow + (size_t)r * DIM + kk0 + k4);
            Bs[r][k4 + 0] = w.x; Bs[r][k4 + 1] = w.y; Bs[r][k4 + 2] = w.z; Bs[r][k4 + 3] = w.w;
        }
        __syncthreads();
#pragma unroll
        for (int k = 0; k < 32; k++) {
            float a[8], b[8];
#pragma unroll
            for (int j = 0; j < 8; j++) { a[j] = As[r0 + j][k]; b[j] = Bs[c0 + j][k]; }
#pragma unroll
            for (int i = 0; i < 8; i++)
#pragma unroll
                for (int j = 0; j < 8; j++)
                    acc[i][j] = fmaf(a[i], b[j], acc[i][j]);
        }
        __syncthreads();
    }
    const float scale = 0.088388347648318447f;  // 1/sqrt(128)
#pragma unroll
    for (int i = 0; i < 8; i++)
#pragma unroll
        for (int j = 0; j < 8; j++) acc[i][j] *= scale;

    // normal tile write
#pragma unroll
    for (int i = 0; i < 8; i++) {
        float4 v0, v1;
        v0.x = acc[i][0]; v0.y = acc[i][1]; v0.z = acc[i][2]; v0.w = acc[i][3];
        v1.x = acc[i][4]; v1.y = acc[i][5]; v1.z = acc[i][6]; v1.w = acc[i][7];
        float* dst = att + (size_t)(ti * 128 + r0 + i) * SEQ + tj * 128 + c0;
        *(float4*)dst = v0;
        *(float4*)(dst + 4) = v1;
    }
    // mirrored (transposed) tile write
    if (ti != tj) {
#pragma unroll
        for (int j = 0; j < 8; j++) {
            float4 v0, v1;
            v0.x = acc[0][j]; v0.y = acc[1][j]; v0.z = acc[2][j]; v0.w = acc[3][j];
            v1.x = acc[4][j]; v1.y = acc[5][j]; v1.z = acc[6][j]; v1.w = acc[7][j];
            float* dst = att + (size_t)(tj * 128 + c0 + j) * SEQ + ti * 128 + r0;
            *(float4*)dst = v0;
            *(float4*)(dst + 4) = v1;
        }
    }
}

// ---------------------------------------------------------------------------
// Row statistics: max, 1/sum(exp(x-max)), and the diagonal softmax value.
// grid 2*8*2048 blocks, block 256 (8 elems/thread).
// ---------------------------------------------------------------------------
__global__ __launch_bounds__(256) void rowstat_kernel()
{
    const int row = blockIdx.x;
    const float* __restrict__ a = g_att + (size_t)row * SEQ;
    const int tid = threadIdx.x;
    float v[8];
    float m = -3.4e38f;
#pragma unroll
    for (int i = 0; i < 8; i++) { v[i] = a[tid + i * 256]; m = fmaxf(m, v[i]); }
    __shared__ float red[256];
    red[tid] = m; __syncthreads();
    for (int s = 128; s > 0; s >>= 1) {
        if (tid < s) red[tid] = fmaxf(red[tid], red[tid + s]);
        __syncthreads();
    }
    m = red[0];
    __syncthreads();
    float sum = 0.f;
#pragma unroll
    for (int i = 0; i < 8; i++) sum += expf(v[i] - m);
    red[tid] = sum; __syncthreads();
    for (int s = 128; s > 0; s >>= 1) {
        if (tid < s) red[tid] += red[tid + s];
        __syncthreads();
    }
    if (tid == 0) {
        float inv = 1.f / red[0];
        g_rowmax[row] = m;
        g_rowinv[row] = inv;
        int l = row & (SEQ - 1);
        g_diag[row] = expf(a[l] - m) * inv;
    }
}

// ---------------------------------------------------------------------------
// Column sums of the softmax matrix, in 4 deterministic L-chunks.
// grid (8, 16, 4), block 256 (one column per thread).
// ---------------------------------------------------------------------------
__global__ __launch_bounds__(256) void colsum_kernel()
{
    const int col = blockIdx.x * 256 + threadIdx.x;
    const int pn = blockIdx.y;
    const int lc = blockIdx.z;
    const float* __restrict__ att = g_att + (size_t)pn * SEQ * SEQ;
    const float* __restrict__ rmax = g_rowmax + pn * SEQ;
    const float* __restrict__ rinv = g_rowinv + pn * SEQ;
    __shared__ float smax[256], sinv[256];
    float acc = 0.f;
    const int l0 = lc * LCHUNK;
    for (int c = 0; c < LCHUNK; c += 256) {
        __syncthreads();
        smax[threadIdx.x] = rmax[l0 + c + threadIdx.x];
        sinv[threadIdx.x] = rinv[l0 + c + threadIdx.x];
        __syncthreads();
        const float* base = att + (size_t)(l0 + c) * SEQ + col;
#pragma unroll 8
        for (int l = 0; l < 256; l++)
            acc += expf(base[(size_t)l * SEQ] - smax[l]) * sinv[l];
    }
    g_part[((size_t)lc * NPAIR * NBATCH + pn) * SEQ + col] = acc;
}

// ---------------------------------------------------------------------------
// Per (pair,batch): final score (fixed-order partial sum minus diagonal),
// bitonic sort 2048 elems, theta = k-th smallest (k=1024).
// grid 16, block 1024.
// ---------------------------------------------------------------------------
__global__ __launch_bounds__(1024) void select_kernel()
{
    const int pn = blockIdx.x;
    __shared__ float s[2048];
    const int tid = threadIdx.x;
    const int PN = NPAIR * NBATCH;
    for (int i = tid; i < SEQ; i += 1024) {
        float v = g_part[((size_t)0 * PN + pn) * SEQ + i]
                + g_part[((size_t)1 * PN + pn) * SEQ + i]
                + g_part[((size_t)2 * PN + pn) * SEQ + i]
                + g_part[((size_t)3 * PN + pn) * SEQ + i]
                - g_diag[pn * SEQ + i];
        g_score[pn * SEQ + i] = v;
        s[i] = v;
    }
    __syncthreads();
    for (int k = 2; k <= 2048; k <<= 1) {
        for (int j = k >> 1; j > 0; j >>= 1) {
            for (int idx = tid; idx < 2048; idx += 1024) {
                int ixj = idx ^ j;
                if (ixj > idx) {
                    bool up = ((idx & k) == 0);
                    float a = s[idx], b = s[ixj];
                    if ((a > b) == up) { s[idx] = b; s[ixj] = a; }
                }
            }
            __syncthreads();
        }
    }
    if (tid == 0) g_theta[pn] = s[1023];   // 1024-th smallest
}

// ---------------------------------------------------------------------------
// Output blend. mask = score <= theta (bottom-k, matching reference ties).
// mt1 = mt & ~mf  -> out_t = 0.5*(x_t + x_f) else x_t (exact). Same for f.
// grid 2048, block 256 (one float4 of both outputs per thread).
// ---------------------------------------------------------------------------
__global__ __launch_bounds__(256) void output_kernel(
    const float* __restrict__ xt, const float* __restrict__ xf, float* __restrict__ out)
{
    const int idx = blockIdx.x * 256 + threadIdx.x;  // float4 index, 524288 total
    const int nl = idx >> 5;                          // 32 float4 per D-row
    const int n = nl >> 11;
    const int l = nl & (SEQ - 1);
    const float st = g_score[n * SEQ + l];
    const float sf = g_score[(NBATCH + n) * SEQ + l];
    const bool mt = st <= g_theta[n];
    const bool mf = sf <= g_theta[NBATCH + n];
    const bool mt1 = mt && !mf;
    const bool mf1 = mf && !mt;
    const float4 vt = ((const float4*)xt)[idx];
    const float4 vf = ((const float4*)xf)[idx];
    float4 avg;
    avg.x = 0.5f * (vt.x + vf.x);
    avg.y = 0.5f * (vt.y + vf.y);
    avg.z = 0.5f * (vt.z + vf.z);
    avg.w = 0.5f * (vt.w + vf.w);
    ((float4*)out)[idx] = mt1 ? avg : vt;
    ((float4*)out)[(size_t)NBATCH * SEQ * (DIM / 4) + idx] = mf1 ? avg : vf;
}

extern "C" void kernel_launch(void* const* d_in, const int* in_sizes, int n_in,
                              void* d_out, int out_size)
{
    const float* xt = (const float*)d_in[0];
    const float* xf = (const float*)d_in[1];
    const float* W  = (const float*)d_in[2];
    const float* b  = (const float*)d_in[3];
    float* out = (float*)d_out;

    proj_kernel<<<dim3(128, 2), 256>>>(xt, xf, W, b);
    att_kernel<<<dim3(136, 8, 2), 256>>>();
    rowstat_kernel<<<NPAIR * NBATCH * SEQ, 256>>>();
    colsum_kernel<<<dim3(8, 16, 4), 256>>>();
    select_kernel<<<16, 1024>>>();
    output_kernel<<<2048, 256>>>(xt, xf, out);
}

// round 4
// speedup vs baseline: 1.0194x; 1.0180x over previous
#include <cuda_runtime.h>

#define NBATCH 8
#define SEQ 2048
#define DIM 128
#define NPAIR 2
#define LCHUNKS 8
#define LCHUNK (SEQ / LCHUNKS)

// Scratch (device globals -- no allocation allowed in kernel_launch)
__device__ float g_proj[(size_t)NPAIR * NBATCH * SEQ * DIM];       // 16 MB
__device__ float g_att[(size_t)NPAIR * NBATCH * SEQ * SEQ];        // 268 MB
__device__ float g_rowmax[NPAIR * NBATCH * SEQ];
__device__ float g_rowinv[NPAIR * NBATCH * SEQ];
__device__ float g_diag[NPAIR * NBATCH * SEQ];
__device__ float g_part[LCHUNKS * NPAIR * NBATCH * SEQ];
__device__ float g_score[NPAIR * NBATCH * SEQ];
__device__ float g_theta[NPAIR * NBATCH];

// ---- f32x2 packed helpers (SASS FFMA2 -- exact fp32, 2x throughput) -------
__device__ __forceinline__ unsigned long long pack_dup(float a) {
    unsigned long long r;
    asm("mov.b64 %0, {%1, %1};" : "=l"(r) : "f"(a));
    return r;
}
__device__ __forceinline__ void fma2(unsigned long long& d,
                                     unsigned long long a, unsigned long long b) {
    asm("fma.rn.f32x2 %0, %1, %2, %0;" : "+l"(d) : "l"(a), "l"(b));
}
__device__ __forceinline__ void unpack2(unsigned long long v, float& lo, float& hi) {
    asm("mov.b64 {%0, %1}, %2;" : "=f"(lo), "=f"(hi) : "l"(v));
}

// ---------------------------------------------------------------------------
// Core 128x128x128 fp32 tile MAC with f32x2 packed FMA.
// As: [r][k] padded; sB: [k][c] padded (b-pairs contiguous -> LDS.64).
// Each thread (tx=tid&15, ty=tid>>4) owns rows ty*8..+7, cols tx*8..+7.
// ---------------------------------------------------------------------------
struct TileSmem {
    float As[128][33];
    float sB[32][130];   // one 32-wide k-chunk, k-major, c contiguous
};

__device__ __forceinline__ void tile_mac_f32x2(
    TileSmem* s, const float* __restrict__ Arow, const float* __restrict__ Brow,
    unsigned long long acc2[8][4], int tid, int r0, int c0)
{
    // Stage A tile once (all 128 k's), B chunk-by-chunk (k-major layout).
    for (int kk0 = 0; kk0 < DIM; kk0 += 32) {
#pragma unroll
        for (int it = 0; it < 4; it++) {
            int idx4 = it * 256 + tid;
            int r = idx4 >> 3;
            int k4 = (idx4 & 7) * 4;
            float4 v = *(const float4*)(Arow + (size_t)r * DIM + kk0 + k4);
            s->As[r][k4 + 0] = v.x; s->As[r][k4 + 1] = v.y;
            s->As[r][k4 + 2] = v.z; s->As[r][k4 + 3] = v.w;
            float4 w = *(const float4*)(Brow + (size_t)r * DIM + kk0 + k4);
            s->sB[k4 + 0][r] = w.x; s->sB[k4 + 1][r] = w.y;
            s->sB[k4 + 2][r] = w.z; s->sB[k4 + 3][r] = w.w;
        }
        __syncthreads();
#pragma unroll 4
        for (int k = 0; k < 32; k++) {
            unsigned long long a2[8], b2[4];
#pragma unroll
            for (int i = 0; i < 8; i++) a2[i] = pack_dup(s->As[r0 + i][k]);
#pragma unroll
            for (int j = 0; j < 4; j++)
                b2[j] = *(const unsigned long long*)&s->sB[k][c0 + 2 * j];
#pragma unroll
            for (int i = 0; i < 8; i++)
#pragma unroll
                for (int j = 0; j < 4; j++)
                    fma2(acc2[i][j], a2[i], b2[j]);
        }
        __syncthreads();
    }
}

// ---------------------------------------------------------------------------
// Projection: P = X @ W^T + b   for both x_t (p=0) and x_f (p=1)
// grid (128, 2), block 256.
// ---------------------------------------------------------------------------
__global__ __launch_bounds__(256) void proj_kernel(
    const float* __restrict__ xt, const float* __restrict__ xf,
    const float* __restrict__ W, const float* __restrict__ bias)
{
    __shared__ TileSmem s;
    const int p = blockIdx.y;
    const float* __restrict__ X = (p == 0) ? xt : xf;
    const int rbase = blockIdx.x * 128;
    const int tid = threadIdx.x;
    const int tx = tid & 15, ty = tid >> 4;
    const int r0 = ty * 8, c0 = tx * 8;
    unsigned long long acc2[8][4];
#pragma unroll
    for (int i = 0; i < 8; i++)
#pragma unroll
        for (int j = 0; j < 4; j++) acc2[i][j] = 0ull;

    tile_mac_f32x2(&s, X + (size_t)rbase * DIM, W, acc2, tid, r0, c0);

    float bv[8];
#pragma unroll
    for (int j = 0; j < 8; j++) bv[j] = bias[c0 + j];
    float* out = g_proj + ((size_t)p * NBATCH * SEQ + rbase) * DIM;
#pragma unroll
    for (int i = 0; i < 8; i++) {
        float a[8];
#pragma unroll
        for (int j = 0; j < 4; j++) unpack2(acc2[i][j], a[2 * j], a[2 * j + 1]);
        float4 v0, v1;
        v0.x = a[0] + bv[0]; v0.y = a[1] + bv[1]; v0.z = a[2] + bv[2]; v0.w = a[3] + bv[3];
        v1.x = a[4] + bv[4]; v1.y = a[5] + bv[5]; v1.z = a[6] + bv[6]; v1.w = a[7] + bv[7];
        float* dst = out + (size_t)(r0 + i) * DIM + c0;
        *(float4*)dst = v0;
        *(float4*)(dst + 4) = v1;
    }
}

// ---------------------------------------------------------------------------
// Attention logits: att = scale * P P^T (symmetric: upper-tri tiles, mirrored)
// grid (136, 8, 2), block 256.
// ---------------------------------------------------------------------------
__global__ __launch_bounds__(256) void att_kernel()
{
    __shared__ TileSmem s;
    int t = blockIdx.x;
    int ti = 0;
    while (t >= 16 - ti) { t -= 16 - ti; ti++; }
    const int tj = ti + t;
    const int n = blockIdx.y, p = blockIdx.z;
    const float* __restrict__ P = g_proj + ((size_t)p * NBATCH + n) * SEQ * DIM;
    float* __restrict__ att = g_att + ((size_t)p * NBATCH + n) * SEQ * SEQ;
    const int tid = threadIdx.x;
    const int tx = tid & 15, ty = tid >> 4;
    const int r0 = ty * 8, c0 = tx * 8;
    unsigned long long acc2[8][4];
#pragma unroll
    for (int i = 0; i < 8; i++)
#pragma unroll
        for (int j = 0; j < 4; j++) acc2[i][j] = 0ull;

    tile_mac_f32x2(&s, P + (size_t)ti * 128 * DIM, P + (size_t)tj * 128 * DIM,
                   acc2, tid, r0, c0);

    const float scale = 0.088388347648318447f;  // 1/sqrt(128)
    float acc[8][8];
#pragma unroll
    for (int i = 0; i < 8; i++) {
#pragma unroll
        for (int j = 0; j < 4; j++) unpack2(acc2[i][j], acc[i][2 * j], acc[i][2 * j + 1]);
#pragma unroll
        for (int j = 0; j < 8; j++) acc[i][j] *= scale;
    }

    // normal tile write
#pragma unroll
    for (int i = 0; i < 8; i++) {
        float4 v0, v1;
        v0.x = acc[i][0]; v0.y = acc[i][1]; v0.z = acc[i][2]; v0.w = acc[i][3];
        v1.x = acc[i][4]; v1.y = acc[i][5]; v1.z = acc[i][6]; v1.w = acc[i][7];
        float* dst = att + (size_t)(ti * 128 + r0 + i) * SEQ + tj * 128 + c0;
        *(float4*)dst = v0;
        *(float4*)(dst + 4) = v1;
    }
    // mirrored (transposed) tile write
    if (ti != tj) {
#pragma unroll
        for (int j = 0; j < 8; j++) {
            float4 v0, v1;
            v0.x = acc[0][j]; v0.y = acc[1][j]; v0.z = acc[2][j]; v0.w = acc[3][j];
            v1.x = acc[4][j]; v1.y = acc[5][j]; v1.z = acc[6][j]; v1.w = acc[7][j];
            float* dst = att + (size_t)(tj * 128 + c0 + j) * SEQ + ti * 128 + r0;
            *(float4*)dst = v0;
            *(float4*)(dst + 4) = v1;
        }
    }
}

// ---------------------------------------------------------------------------
// Row statistics: max, 1/sum(exp(x-max)), and the diagonal softmax value.
// grid 2*8*2048 blocks, block 256 (8 elems/thread).
// ---------------------------------------------------------------------------
__global__ __launch_bounds__(256) void rowstat_kernel()
{
    const int row = blockIdx.x;
    const float* __restrict__ a = g_att + (size_t)row * SEQ;
    const int tid = threadIdx.x;
    float v[8];
    float m = -3.4e38f;
#pragma unroll
    for (int i = 0; i < 8; i++) { v[i] = a[tid + i * 256]; m = fmaxf(m, v[i]); }
    __shared__ float red[256];
    red[tid] = m; __syncthreads();
    for (int s = 128; s > 0; s >>= 1) {
        if (tid < s) red[tid] = fmaxf(red[tid], red[tid + s]);
        __syncthreads();
    }
    m = red[0];
    __syncthreads();
    float sum = 0.f;
#pragma unroll
    for (int i = 0; i < 8; i++) sum += expf(v[i] - m);
    red[tid] = sum; __syncthreads();
    for (int s = 128; s > 0; s >>= 1) {
        if (tid < s) red[tid] += red[tid + s];
        __syncthreads();
    }
    if (tid == 0) {
        float inv = 1.f / red[0];
        g_rowmax[row] = m;
        g_rowinv[row] = inv;
        int l = row & (SEQ - 1);
        g_diag[row] = expf(a[l] - m) * inv;
    }
}

// ---------------------------------------------------------------------------
// Column sums of the softmax matrix, in 8 deterministic L-chunks.
// grid (8, 16, 8), block 256 (one column per thread, 256 rows per chunk).
// ---------------------------------------------------------------------------
__global__ __launch_bounds__(256) void colsum_kernel()
{
    const int col = blockIdx.x * 256 + threadIdx.x;
    const int pn = blockIdx.y;
    const int lc = blockIdx.z;
    const float* __restrict__ att = g_att + (size_t)pn * SEQ * SEQ;
    const float* __restrict__ rmax = g_rowmax + pn * SEQ;
    const float* __restrict__ rinv = g_rowinv + pn * SEQ;
    __shared__ float smax[LCHUNK], sinv[LCHUNK];
    const int l0 = lc * LCHUNK;
    smax[threadIdx.x] = rmax[l0 + threadIdx.x];
    sinv[threadIdx.x] = rinv[l0 + threadIdx.x];
    __syncthreads();
    const float* base = att + (size_t)l0 * SEQ + col;
    float acc = 0.f;
#pragma unroll 8
    for (int l = 0; l < LCHUNK; l++)
        acc += expf(base[(size_t)l * SEQ] - smax[l]) * sinv[l];
    g_part[((size_t)lc * NPAIR * NBATCH + pn) * SEQ + col] = acc;
}

// ---------------------------------------------------------------------------
// Per (pair,batch): final score (fixed-order partial sum minus diagonal),
// bitonic sort 2048 elems, theta = k-th smallest (k=1024).
// grid 16, block 1024.
// ---------------------------------------------------------------------------
__global__ __launch_bounds__(1024) void select_kernel()
{
    const int pn = blockIdx.x;
    __shared__ float s[2048];
    const int tid = threadIdx.x;
    const int PN = NPAIR * NBATCH;
    for (int i = tid; i < SEQ; i += 1024) {
        float v = 0.f;
#pragma unroll
        for (int c = 0; c < LCHUNKS; c++)
            v += g_part[((size_t)c * PN + pn) * SEQ + i];
        v -= g_diag[pn * SEQ + i];
        g_score[pn * SEQ + i] = v;
        s[i] = v;
    }
    __syncthreads();
    for (int k = 2; k <= 2048; k <<= 1) {
        for (int j = k >> 1; j > 0; j >>= 1) {
            for (int idx = tid; idx < 2048; idx += 1024) {
                int ixj = idx ^ j;
                if (ixj > idx) {
                    bool up = ((idx & k) == 0);
                    float a = s[idx], b = s[ixj];
                    if ((a > b) == up) { s[idx] = b; s[ixj] = a; }
                }
            }
            __syncthreads();
        }
    }
    if (tid == 0) g_theta[pn] = s[1023];   // 1024-th smallest
}

// ---------------------------------------------------------------------------
// Output blend. mask = score <= theta (bottom-k, matching reference ties).
// mt1 = mt & ~mf  -> out_t = 0.5*(x_t + x_f) else x_t (exact). Same for f.
// grid 2048, block 256 (one float4 of both outputs per thread).
// ---------------------------------------------------------------------------
__global__ __launch_bounds__(256) void output_kernel(
    const float* __restrict__ xt, const float* __restrict__ xf, float* __restrict__ out)
{
    const int idx = blockIdx.x * 256 + threadIdx.x;  // float4 index, 524288 total
    const int nl = idx >> 5;                          // 32 float4 per D-row
    const int n = nl >> 11;
    const int l = nl & (SEQ - 1);
    const float st = g_score[n * SEQ + l];
    const float sf = g_score[(NBATCH + n) * SEQ + l];
    const bool mt = st <= g_theta[n];
    const bool mf = sf <= g_theta[NBATCH + n];
    const bool mt1 = mt && !mf;
    const bool mf1 = mf && !mt;
    const float4 vt = ((const float4*)xt)[idx];
    const float4 vf = ((const float4*)xf)[idx];
    float4 avg;
    avg.x = 0.5f * (vt.x + vf.x);
    avg.y = 0.5f * (vt.y + vf.y);
    avg.z = 0.5f * (vt.z + vf.z);
    avg.w = 0.5f * (vt.w + vf.w);
    ((float4*)out)[idx] = mt1 ? avg : vt;
    ((float4*)out)[(size_t)NBATCH * SEQ * (DIM / 4) + idx] = mf1 ? avg : vf;
}

extern "C" void kernel_launch(void* const* d_in, const int* in_sizes, int n_in,
                              void* d_out, int out_size)
{
    const float* xt = (const float*)d_in[0];
    const float* xf = (const float*)d_in[1];
    const float* W  = (const float*)d_in[2];
    const float* b  = (const float*)d_in[3];
    float* out = (float*)d_out;

    proj_kernel<<<dim3(128, 2), 256>>>(xt, xf, W, b);
    att_kernel<<<dim3(136, 8, 2), 256>>>();
    rowstat_kernel<<<NPAIR * NBATCH * SEQ, 256>>>();
    colsum_kernel<<<dim3(8, 16, LCHUNKS), 256>>>();
    select_kernel<<<16, 1024>>>();
    output_kernel<<<2048, 256>>>(xt, xf, out);
}

// round 6
// speedup vs baseline: 1.2958x; 1.2711x over previous
#include <cuda_runtime.h>

#define NBATCH 8
#define SEQ 2048
#define DIM 128
#define NPAIR 2
#define LCHUNKS 8
#define LCHUNK (SEQ / LCHUNKS)

// Scratch (device globals -- no allocation allowed in kernel_launch)
__device__ float g_phi[(size_t)NPAIR * NBATCH * SEQ * DIM];        // 16 MB tf32-hi
__device__ float g_plo[(size_t)NPAIR * NBATCH * SEQ * DIM];        // 16 MB tf32-lo
__device__ float g_att[(size_t)NPAIR * NBATCH * SEQ * SEQ];        // 268 MB
__device__ float g_rowmax[NPAIR * NBATCH * SEQ];
__device__ float g_rowinv[NPAIR * NBATCH * SEQ];
__device__ float g_diag[NPAIR * NBATCH * SEQ];
__device__ float g_part[LCHUNKS * NPAIR * NBATCH * SEQ];
__device__ float g_score[NPAIR * NBATCH * SEQ];
__device__ float g_theta[NPAIR * NBATCH];

__device__ __forceinline__ float to_tf32(float x) {
    float r;
    asm("cvt.rna.tf32.f32 %0, %1;" : "=f"(r) : "f"(x));
    return r;
}

// m16n8k8 tf32 MMA (Ampere-era path; needs no sm_103a feature)
__device__ __forceinline__ void mma_tf32(float d[4], const unsigned a[4],
                                         const unsigned b[2]) {
    asm volatile(
        "mma.sync.aligned.m16n8k8.row.col.f32.tf32.tf32.f32 "
        "{%0,%1,%2,%3}, {%4,%5,%6,%7}, {%8,%9}, {%0,%1,%2,%3};"
        : "+f"(d[0]), "+f"(d[1]), "+f"(d[2]), "+f"(d[3])
        : "r"(a[0]), "r"(a[1]), "r"(a[2]), "r"(a[3]), "r"(b[0]), "r"(b[1]));
}

// ---------------------------------------------------------------------------
// Projection: P = X @ W^T + b, then split into tf32 hi/lo planes.
// grid (128, 2), block 256. Plain fp32 FMA (exact).
// ---------------------------------------------------------------------------
__global__ __launch_bounds__(256) void proj_kernel(
    const float* __restrict__ xt, const float* __restrict__ xf,
    const float* __restrict__ W, const float* __restrict__ bias)
{
    __shared__ float As[128][33];
    __shared__ float Bs[128][33];
    const int p = blockIdx.y;
    const float* __restrict__ X = (p == 0) ? xt : xf;
    const int rbase = blockIdx.x * 128;
    const int tid = threadIdx.x;
    const int tx = tid & 15, ty = tid >> 4;
    const int r0 = ty * 8, c0 = tx * 8;
    float acc[8][8];
#pragma unroll
    for (int i = 0; i < 8; i++)
#pragma unroll
        for (int j = 0; j < 8; j++) acc[i][j] = 0.f;

    for (int kk0 = 0; kk0 < DIM; kk0 += 32) {
#pragma unroll
        for (int it = 0; it < 4; it++) {
            int idx4 = it * 256 + tid;
            int r = idx4 >> 3;
            int k4 = (idx4 & 7) * 4;
            float4 v = *(const float4*)(X + (size_t)(rbase + r) * DIM + kk0 + k4);
            As[r][k4 + 0] = v.x; As[r][k4 + 1] = v.y; As[r][k4 + 2] = v.z; As[r][k4 + 3] = v.w;
            float4 w = *(const float4*)(W + (size_t)r * DIM + kk0 + k4);
            Bs[r][k4 + 0] = w.x; Bs[r][k4 + 1] = w.y; Bs[r][k4 + 2] = w.z; Bs[r][k4 + 3] = w.w;
        }
        __syncthreads();
#pragma unroll
        for (int k = 0; k < 32; k++) {
            float a[8], b[8];
#pragma unroll
            for (int j = 0; j < 8; j++) { a[j] = As[r0 + j][k]; b[j] = Bs[c0 + j][k]; }
#pragma unroll
            for (int i = 0; i < 8; i++)
#pragma unroll
                for (int j = 0; j < 8; j++)
                    acc[i][j] = fmaf(a[i], b[j], acc[i][j]);
        }
        __syncthreads();
    }
    float bv[8];
#pragma unroll
    for (int j = 0; j < 8; j++) bv[j] = bias[c0 + j];
    const size_t obase = ((size_t)p * NBATCH * SEQ + rbase) * DIM;
#pragma unroll
    for (int i = 0; i < 8; i++) {
        float hi[8], lo[8];
#pragma unroll
        for (int j = 0; j < 8; j++) {
            float v = acc[i][j] + bv[j];
            hi[j] = to_tf32(v);
            lo[j] = to_tf32(v - hi[j]);
        }
        float* dh = g_phi + obase + (size_t)(r0 + i) * DIM + c0;
        float* dl = g_plo + obase + (size_t)(r0 + i) * DIM + c0;
        *(float4*)dh       = make_float4(hi[0], hi[1], hi[2], hi[3]);
        *(float4*)(dh + 4) = make_float4(hi[4], hi[5], hi[6], hi[7]);
        *(float4*)dl       = make_float4(lo[0], lo[1], lo[2], lo[3]);
        *(float4*)(dl + 4) = make_float4(lo[4], lo[5], lo[6], lo[7]);
    }
}

// ---------------------------------------------------------------------------
// Attention logits via mma.sync tf32 3x-split: att = scale * P P^T
// (symmetric: upper-tri tiles, mirrored). grid (136, 8, 2), block 256.
// 8 warps, each computes a 32x64 sub-tile of the 128x128 output as
// 2 (m16) x 8 (n8) mma fragments. Smem rows padded to 36 floats so
// fragment loads hit banks 4*(lane>>2)+(lane&3): conflict-free.
// ---------------------------------------------------------------------------
#define SPAD 36
#define T_SZ (128 * SPAD)          // floats per staged tensor (k-chunk of 32)
#define ATT_SMEM (4 * T_SZ * 4)    // bytes: Ah, Al, Bh, Bl

struct Frag { float v[2][8][4]; };

__device__ __forceinline__ void mac_chunk(const float* __restrict__ A,
                                          const float* __restrict__ B,
                                          Frag& f, int wr, int wc, int lq, int lr)
{
#pragma unroll
    for (int k8 = 0; k8 < 4; k8++) {
        const int k0 = k8 * 8;
        unsigned a[2][4], b[8][2];
#pragma unroll
        for (int mt = 0; mt < 2; mt++) {
            const int m = wr * 32 + mt * 16;
            a[mt][0] = __float_as_uint(A[(m + lq) * SPAD + k0 + lr]);
            a[mt][1] = __float_as_uint(A[(m + 8 + lq) * SPAD + k0 + lr]);
            a[mt][2] = __float_as_uint(A[(m + lq) * SPAD + k0 + 4 + lr]);
            a[mt][3] = __float_as_uint(A[(m + 8 + lq) * SPAD + k0 + 4 + lr]);
        }
#pragma unroll
        for (int nt = 0; nt < 8; nt++) {
            const int n = wc * 64 + nt * 8 + lq;
            b[nt][0] = __float_as_uint(B[n * SPAD + k0 + lr]);
            b[nt][1] = __float_as_uint(B[n * SPAD + k0 + 4 + lr]);
        }
#pragma unroll
        for (int mt = 0; mt < 2; mt++)
#pragma unroll
            for (int nt = 0; nt < 8; nt++)
                mma_tf32(f.v[mt][nt], a[mt], b[nt]);
    }
}

__global__ __launch_bounds__(256) void att_kernel()
{
    extern __shared__ float sm[];
    float* sAh = sm;
    float* sAl = sm + T_SZ;
    float* sBh = sm + 2 * T_SZ;
    float* sBl = sm + 3 * T_SZ;

    int t = blockIdx.x;
    int ti = 0;
    while (t >= 16 - ti) { t -= 16 - ti; ti++; }
    const int tj = ti + t;
    const int pn = blockIdx.z * NBATCH + blockIdx.y;
    const size_t pbase = (size_t)pn * SEQ * DIM;
    const float* __restrict__ Ah = g_phi + pbase + (size_t)ti * 128 * DIM;
    const float* __restrict__ Al = g_plo + pbase + (size_t)ti * 128 * DIM;
    const float* __restrict__ Bh = g_phi + pbase + (size_t)tj * 128 * DIM;
    const float* __restrict__ Bl = g_plo + pbase + (size_t)tj * 128 * DIM;
    float* __restrict__ att = g_att + (size_t)pn * SEQ * SEQ;

    const int tid = threadIdx.x;
    const int wid = tid >> 5, lane = tid & 31;
    const int lq = lane >> 2, lr = lane & 3;
    const int wr = wid & 3, wc = wid >> 2;

    Frag f;
#pragma unroll
    for (int mt = 0; mt < 2; mt++)
#pragma unroll
        for (int nt = 0; nt < 8; nt++)
#pragma unroll
            for (int e = 0; e < 4; e++) f.v[mt][nt][e] = 0.f;

    for (int c = 0; c < 4; c++) {
        const int kk0 = c * 32;
#pragma unroll
        for (int it = 0; it < 4; it++) {
            int fidx = it * 256 + tid;
            int r = fidx >> 3;
            int k4 = (fidx & 7) * 4;
            size_t g = (size_t)r * DIM + kk0 + k4;
            int so = r * SPAD + k4;
            *(float4*)&sAh[so] = *(const float4*)(Ah + g);
            *(float4*)&sAl[so] = *(const float4*)(Al + g);
            *(float4*)&sBh[so] = *(const float4*)(Bh + g);
            *(float4*)&sBl[so] = *(const float4*)(Bl + g);
        }
        __syncthreads();
        mac_chunk(sAh, sBh, f, wr, wc, lq, lr);   // hi*hi
        mac_chunk(sAh, sBl, f, wr, wc, lq, lr);   // hi*lo
        mac_chunk(sAl, sBh, f, wr, wc, lq, lr);   // lo*hi
        __syncthreads();
    }

    const float scale = 0.088388347648318447f;  // 1/sqrt(128)
#pragma unroll
    for (int mt = 0; mt < 2; mt++) {
#pragma unroll
        for (int nt = 0; nt < 8; nt++) {
            const int r = wr * 32 + mt * 16 + lq;
            const int cl = wc * 64 + nt * 8 + 2 * lr;
            float v0 = f.v[mt][nt][0] * scale;
            float v1 = f.v[mt][nt][1] * scale;
            float v2 = f.v[mt][nt][2] * scale;
            float v3 = f.v[mt][nt][3] * scale;
            float2 p0 = make_float2(v0, v1);
            float2 p1 = make_float2(v2, v3);
            *(float2*)&att[(size_t)(ti * 128 + r) * SEQ + tj * 128 + cl] = p0;
            *(float2*)&att[(size_t)(ti * 128 + r + 8) * SEQ + tj * 128 + cl] = p1;
            if (ti != tj) {
                att[(size_t)(tj * 128 + cl) * SEQ + ti * 128 + r] = v0;
                att[(size_t)(tj * 128 + cl + 1) * SEQ + ti * 128 + r] = v1;
                att[(size_t)(tj * 128 + cl) * SEQ + ti * 128 + r + 8] = v2;
                att[(size_t)(tj * 128 + cl + 1) * SEQ + ti * 128 + r + 8] = v3;
            }
        }
    }
}

// ---------------------------------------------------------------------------
// Row statistics: max, 1/sum(exp(x-max)), and the diagonal softmax value.
// ---------------------------------------------------------------------------
__global__ __launch_bounds__(256) void rowstat_kernel()
{
    const int row = blockIdx.x;
    const float* __restrict__ a = g_att + (size_t)row * SEQ;
    const int tid = threadIdx.x;
    float v[8];
    float m = -3.4e38f;
#pragma unroll
    for (int i = 0; i < 8; i++) { v[i] = a[tid + i * 256]; m = fmaxf(m, v[i]); }
    __shared__ float red[256];
    red[tid] = m; __syncthreads();
    for (int s = 128; s > 0; s >>= 1) {
        if (tid < s) red[tid] = fmaxf(red[tid], red[tid + s]);
        __syncthreads();
    }
    m = red[0];
    __syncthreads();
    float sum = 0.f;
#pragma unroll
    for (int i = 0; i < 8; i++) sum += expf(v[i] - m);
    red[tid] = sum; __syncthreads();
    for (int s = 128; s > 0; s >>= 1) {
        if (tid < s) red[tid] += red[tid + s];
        __syncthreads();
    }
    if (tid == 0) {
        float inv = 1.f / red[0];
        g_rowmax[row] = m;
        g_rowinv[row] = inv;
        int l = row & (SEQ - 1);
        g_diag[row] = expf(a[l] - m) * inv;
    }
}

// ---------------------------------------------------------------------------
// Column sums of the softmax matrix, in 8 deterministic L-chunks.
// grid (8, 16, 8), block 256.
// ---------------------------------------------------------------------------
__global__ __launch_bounds__(256) void colsum_kernel()
{
    const int col = blockIdx.x * 256 + threadIdx.x;
    const int pn = blockIdx.y;
    const int lc = blockIdx.z;
    const float* __restrict__ att = g_att + (size_t)pn * SEQ * SEQ;
    const float* __restrict__ rmax = g_rowmax + pn * SEQ;
    const float* __restrict__ rinv = g_rowinv + pn * SEQ;
    __shared__ float smax[LCHUNK], sinv[LCHUNK];
    const int l0 = lc * LCHUNK;
    smax[threadIdx.x] = rmax[l0 + threadIdx.x];
    sinv[threadIdx.x] = rinv[l0 + threadIdx.x];
    __syncthreads();
    const float* base = att + (size_t)l0 * SEQ + col;
    float acc = 0.f;
#pragma unroll 8
    for (int l = 0; l < LCHUNK; l++)
        acc += expf(base[(size_t)l * SEQ] - smax[l]) * sinv[l];
    g_part[((size_t)lc * NPAIR * NBATCH + pn) * SEQ + col] = acc;
}

// ---------------------------------------------------------------------------
// Per (pair,batch): final score, bitonic sort, theta = 1024-th smallest.
// ---------------------------------------------------------------------------
__global__ __launch_bounds__(1024) void select_kernel()
{
    const int pn = blockIdx.x;
    __shared__ float s[2048];
    const int tid = threadIdx.x;
    const int PN = NPAIR * NBATCH;
    for (int i = tid; i < SEQ; i += 1024) {
        float v = 0.f;
#pragma unroll
        for (int c = 0; c < LCHUNKS; c++)
            v += g_part[((size_t)c * PN + pn) * SEQ + i];
        v -= g_diag[pn * SEQ + i];
        g_score[pn * SEQ + i] = v;
        s[i] = v;
    }
    __syncthreads();
    for (int k = 2; k <= 2048; k <<= 1) {
        for (int j = k >> 1; j > 0; j >>= 1) {
            for (int idx = tid; idx < 2048; idx += 1024) {
                int ixj = idx ^ j;
                if (ixj > idx) {
                    bool up = ((idx & k) == 0);
                    float a = s[idx], b = s[ixj];
                    if ((a > b) == up) { s[idx] = b; s[ixj] = a; }
                }
            }
            __syncthreads();
        }
    }
    if (tid == 0) g_theta[pn] = s[1023];   // 1024-th smallest
}

// ---------------------------------------------------------------------------
// Output blend.
// ---------------------------------------------------------------------------
__global__ __launch_bounds__(256) void output_kernel(
    const float* __restrict__ xt, const float* __restrict__ xf, float* __restrict__ out)
{
    const int idx = blockIdx.x * 256 + threadIdx.x;
    const int nl = idx >> 5;
    const int n = nl >> 11;
    const int l = nl & (SEQ - 1);
    const float st = g_score[n * SEQ + l];
    const float sf = g_score[(NBATCH + n) * SEQ + l];
    const bool mt = st <= g_theta[n];
    const bool mf = sf <= g_theta[NBATCH + n];
    const bool mt1 = mt && !mf;
    const bool mf1 = mf && !mt;
    const float4 vt = ((const float4*)xt)[idx];
    const float4 vf = ((const float4*)xf)[idx];
    float4 avg;
    avg.x = 0.5f * (vt.x + vf.x);
    avg.y = 0.5f * (vt.y + vf.y);
    avg.z = 0.5f * (vt.z + vf.z);
    avg.w = 0.5f * (vt.w + vf.w);
    ((float4*)out)[idx] = mt1 ? avg : vt;
    ((float4*)out)[(size_t)NBATCH * SEQ * (DIM / 4) + idx] = mf1 ? avg : vf;
}

extern "C" void kernel_launch(void* const* d_in, const int* in_sizes, int n_in,
                              void* d_out, int out_size)
{
    const float* xt = (const float*)d_in[0];
    const float* xf = (const float*)d_in[1];
    const float* W  = (const float*)d_in[2];
    const float* b  = (const float*)d_in[3];
    float* out = (float*)d_out;

    cudaFuncSetAttribute(att_kernel, cudaFuncAttributeMaxDynamicSharedMemorySize,
                         ATT_SMEM);

    proj_kernel<<<dim3(128, 2), 256>>>(xt, xf, W, b);
    att_kernel<<<dim3(136, 8, 2), 256, ATT_SMEM>>>();
    rowstat_kernel<<<NPAIR * NBATCH * SEQ, 256>>>();
    colsum_kernel<<<dim3(8, 16, LCHUNKS), 256>>>();
    select_kernel<<<16, 1024>>>();
    output_kernel<<<2048, 256>>>(xt, xf, out);
}

// round 7
// speedup vs baseline: 1.5394x; 1.1880x over previous
#include <cuda_runtime.h>

#define NBATCH 8
#define SEQ 2048
#define DIM 128
#define NPAIR 2
#define LCHUNKS 8
#define LCHUNK (SEQ / LCHUNKS)

// Scratch (device globals -- no allocation allowed in kernel_launch)
__device__ float g_phi[(size_t)NPAIR * NBATCH * SEQ * DIM];        // 16 MB tf32-hi
__device__ float g_plo[(size_t)NPAIR * NBATCH * SEQ * DIM];        // 16 MB tf32-lo
__device__ float g_att[(size_t)NPAIR * NBATCH * SEQ * SEQ];        // 268 MB (holds E=exp)
__device__ float g_rpart[(size_t)NPAIR * NBATCH * 16 * SEQ];       // 2 MB row-sum partials
__device__ float g_dexp[NPAIR * NBATCH * SEQ];                     // diagonal exp
__device__ float g_rinv[NPAIR * NBATCH * SEQ];
__device__ float g_diag[NPAIR * NBATCH * SEQ];                     // diag softmax value
__device__ float g_part[LCHUNKS * NPAIR * NBATCH * SEQ];
__device__ float g_score[NPAIR * NBATCH * SEQ];
__device__ float g_theta[NPAIR * NBATCH];

__device__ __forceinline__ float to_tf32(float x) {
    float r;
    asm("cvt.rna.tf32.f32 %0, %1;" : "=f"(r) : "f"(x));
    return r;
}

// m16n8k8 tf32 MMA (Ampere-era path; needs no sm_103a feature)
__device__ __forceinline__ void mma_tf32(float d[4], const unsigned a[4],
                                         const unsigned b[2]) {
    asm volatile(
        "mma.sync.aligned.m16n8k8.row.col.f32.tf32.tf32.f32 "
        "{%0,%1,%2,%3}, {%4,%5,%6,%7}, {%8,%9}, {%0,%1,%2,%3};"
        : "+f"(d[0]), "+f"(d[1]), "+f"(d[2]), "+f"(d[3])
        : "r"(a[0]), "r"(a[1]), "r"(a[2]), "r"(a[3]), "r"(b[0]), "r"(b[1]));
}

// ---------------------------------------------------------------------------
// Projection: P = X @ W^T + b, then split into tf32 hi/lo planes.
// grid (128, 2), block 256. Plain fp32 FMA (exact).
// ---------------------------------------------------------------------------
__global__ __launch_bounds__(256) void proj_kernel(
    const float* __restrict__ xt, const float* __restrict__ xf,
    const float* __restrict__ W, const float* __restrict__ bias)
{
    __shared__ float As[128][33];
    __shared__ float Bs[128][33];
    const int p = blockIdx.y;
    const float* __restrict__ X = (p == 0) ? xt : xf;
    const int rbase = blockIdx.x * 128;
    const int tid = threadIdx.x;
    const int tx = tid & 15, ty = tid >> 4;
    const int r0 = ty * 8, c0 = tx * 8;
    float acc[8][8];
#pragma unroll
    for (int i = 0; i < 8; i++)
#pragma unroll
        for (int j = 0; j < 8; j++) acc[i][j] = 0.f;

    for (int kk0 = 0; kk0 < DIM; kk0 += 32) {
#pragma unroll
        for (int it = 0; it < 4; it++) {
            int idx4 = it * 256 + tid;
            int r = idx4 >> 3;
            int k4 = (idx4 & 7) * 4;
            float4 v = *(const float4*)(X + (size_t)(rbase + r) * DIM + kk0 + k4);
            As[r][k4 + 0] = v.x; As[r][k4 + 1] = v.y; As[r][k4 + 2] = v.z; As[r][k4 + 3] = v.w;
            float4 w = *(const float4*)(W + (size_t)r * DIM + kk0 + k4);
            Bs[r][k4 + 0] = w.x; Bs[r][k4 + 1] = w.y; Bs[r][k4 + 2] = w.z; Bs[r][k4 + 3] = w.w;
        }
        __syncthreads();
#pragma unroll
        for (int k = 0; k < 32; k++) {
            float a[8], b[8];
#pragma unroll
            for (int j = 0; j < 8; j++) { a[j] = As[r0 + j][k]; b[j] = Bs[c0 + j][k]; }
#pragma unroll
            for (int i = 0; i < 8; i++)
#pragma unroll
                for (int j = 0; j < 8; j++)
                    acc[i][j] = fmaf(a[i], b[j], acc[i][j]);
        }
        __syncthreads();
    }
    float bv[8];
#pragma unroll
    for (int j = 0; j < 8; j++) bv[j] = bias[c0 + j];
    const size_t obase = ((size_t)p * NBATCH * SEQ + rbase) * DIM;
#pragma unroll
    for (int i = 0; i < 8; i++) {
        float hi[8], lo[8];
#pragma unroll
        for (int j = 0; j < 8; j++) {
            float v = acc[i][j] + bv[j];
            hi[j] = to_tf32(v);
            lo[j] = to_tf32(v - hi[j]);
        }
        float* dh = g_phi + obase + (size_t)(r0 + i) * DIM + c0;
        float* dl = g_plo + obase + (size_t)(r0 + i) * DIM + c0;
        *(float4*)dh       = make_float4(hi[0], hi[1], hi[2], hi[3]);
        *(float4*)(dh + 4) = make_float4(hi[4], hi[5], hi[6], hi[7]);
        *(float4*)dl       = make_float4(lo[0], lo[1], lo[2], lo[3]);
        *(float4*)(dl + 4) = make_float4(lo[4], lo[5], lo[6], lo[7]);
    }
}

// ---------------------------------------------------------------------------
// Attention: E = exp(scale * P P^T) via mma.sync tf32 3x-split.
// Symmetric: upper-tri tiles, mirrored stores. Epilogue additionally emits
// deterministic per-tile row-sum partials (tile (ti,tj) owns slot tj for
// ti-block rows and slot ti for tj-block rows) and the diagonal exp values.
// grid (136, 8, 2), block 256. 8 warps x (32x64) fragments.
// ---------------------------------------------------------------------------
#define SPAD 36
#define T_SZ (128 * SPAD)          // floats per staged tensor (k-chunk of 32)
#define ATT_SMEM (4 * T_SZ * 4)    // bytes: Ah, Al, Bh, Bl

struct Frag { float v[2][8][4]; };

__device__ __forceinline__ void mac_chunk(const float* __restrict__ A,
                                          const float* __restrict__ B,
                                          Frag& f, int wr, int wc, int lq, int lr)
{
#pragma unroll
    for (int k8 = 0; k8 < 4; k8++) {
        const int k0 = k8 * 8;
        unsigned a[2][4], b[8][2];
#pragma unroll
        for (int mt = 0; mt < 2; mt++) {
            const int m = wr * 32 + mt * 16;
            a[mt][0] = __float_as_uint(A[(m + lq) * SPAD + k0 + lr]);
            a[mt][1] = __float_as_uint(A[(m + 8 + lq) * SPAD + k0 + lr]);
            a[mt][2] = __float_as_uint(A[(m + lq) * SPAD + k0 + 4 + lr]);
            a[mt][3] = __float_as_uint(A[(m + 8 + lq) * SPAD + k0 + 4 + lr]);
        }
#pragma unroll
        for (int nt = 0; nt < 8; nt++) {
            const int n = wc * 64 + nt * 8 + lq;
            b[nt][0] = __float_as_uint(B[n * SPAD + k0 + lr]);
            b[nt][1] = __float_as_uint(B[n * SPAD + k0 + 4 + lr]);
        }
#pragma unroll
        for (int mt = 0; mt < 2; mt++)
#pragma unroll
            for (int nt = 0; nt < 8; nt++)
                mma_tf32(f.v[mt][nt], a[mt], b[nt]);
    }
}

__global__ __launch_bounds__(256) void att_kernel()
{
    extern __shared__ float sm[];
    float* sAh = sm;
    float* sAl = sm + T_SZ;
    float* sBh = sm + 2 * T_SZ;
    float* sBl = sm + 3 * T_SZ;

    int t = blockIdx.x;
    int ti = 0;
    while (t >= 16 - ti) { t -= 16 - ti; ti++; }
    const int tj = ti + t;
    const int pn = blockIdx.z * NBATCH + blockIdx.y;
    const size_t pbase = (size_t)pn * SEQ * DIM;
    const float* __restrict__ Ah = g_phi + pbase + (size_t)ti * 128 * DIM;
    const float* __restrict__ Al = g_plo + pbase + (size_t)ti * 128 * DIM;
    const float* __restrict__ Bh = g_phi + pbase + (size_t)tj * 128 * DIM;
    const float* __restrict__ Bl = g_plo + pbase + (size_t)tj * 128 * DIM;
    float* __restrict__ att = g_att + (size_t)pn * SEQ * SEQ;

    const int tid = threadIdx.x;
    const int wid = tid >> 5, lane = tid & 31;
    const int lq = lane >> 2, lr = lane & 3;
    const int wr = wid & 3, wc = wid >> 2;

    Frag f;
#pragma unroll
    for (int mt = 0; mt < 2; mt++)
#pragma unroll
        for (int nt = 0; nt < 8; nt++)
#pragma unroll
            for (int e = 0; e < 4; e++) f.v[mt][nt][e] = 0.f;

    for (int c = 0; c < 4; c++) {
        const int kk0 = c * 32;
#pragma unroll
        for (int it = 0; it < 4; it++) {
            int fidx = it * 256 + tid;
            int r = fidx >> 3;
            int k4 = (fidx & 7) * 4;
            size_t g = (size_t)r * DIM + kk0 + k4;
            int so = r * SPAD + k4;
            *(float4*)&sAh[so] = *(const float4*)(Ah + g);
            *(float4*)&sAl[so] = *(const float4*)(Al + g);
            *(float4*)&sBh[so] = *(const float4*)(Bh + g);
            *(float4*)&sBl[so] = *(const float4*)(Bl + g);
        }
        __syncthreads();
        mac_chunk(sAh, sBh, f, wr, wc, lq, lr);   // hi*hi
        mac_chunk(sAh, sBl, f, wr, wc, lq, lr);   // hi*lo
        mac_chunk(sAl, sBh, f, wr, wc, lq, lr);   // lo*hi
        __syncthreads();
    }

    // ---- epilogue: E = exp(scale*a), stores + deterministic partial sums ---
    const float scale = 0.088388347648318447f;  // 1/sqrt(128)
    float rp[4] = {0.f, 0.f, 0.f, 0.f};        // row partials (this thread's 4 rows)
    float cp0[8], cp1[8];                       // col partials (even/odd col per nt)
#pragma unroll
    for (int nt = 0; nt < 8; nt++) { cp0[nt] = 0.f; cp1[nt] = 0.f; }

#pragma unroll
    for (int mt = 0; mt < 2; mt++) {
#pragma unroll
        for (int nt = 0; nt < 8; nt++) {
            const int rl = wr * 32 + mt * 16 + lq;          // local row
            const int cl = wc * 64 + nt * 8 + 2 * lr;       // local col
            const float e0 = expf(f.v[mt][nt][0] * scale);
            const float e1 = expf(f.v[mt][nt][1] * scale);
            const float e2 = expf(f.v[mt][nt][2] * scale);
            const float e3 = expf(f.v[mt][nt][3] * scale);
            *(float2*)&att[(size_t)(ti * 128 + rl) * SEQ + tj * 128 + cl] =
                make_float2(e0, e1);
            *(float2*)&att[(size_t)(ti * 128 + rl + 8) * SEQ + tj * 128 + cl] =
                make_float2(e2, e3);
            if (ti != tj) {
                att[(size_t)(tj * 128 + cl) * SEQ + ti * 128 + rl] = e0;
                att[(size_t)(tj * 128 + cl + 1) * SEQ + ti * 128 + rl] = e1;
                att[(size_t)(tj * 128 + cl) * SEQ + ti * 128 + rl + 8] = e2;
                att[(size_t)(tj * 128 + cl + 1) * SEQ + ti * 128 + rl + 8] = e3;
            } else {
                // diagonal exp values
                if (rl == cl)         g_dexp[pn * SEQ + ti * 128 + rl] = e0;
                if (rl == cl + 1)     g_dexp[pn * SEQ + ti * 128 + rl] = e1;
                if (rl + 8 == cl)     g_dexp[pn * SEQ + ti * 128 + rl + 8] = e2;
                if (rl + 8 == cl + 1) g_dexp[pn * SEQ + ti * 128 + rl + 8] = e3;
            }
            rp[mt * 2 + 0] += e0 + e1;
            rp[mt * 2 + 1] += e2 + e3;
            cp0[nt] += e0 + e2;
            cp1[nt] += e1 + e3;
        }
    }

    // row partials: reduce over lr (4 lanes hold different columns, same row)
#pragma unroll
    for (int i = 0; i < 4; i++) {
        rp[i] += __shfl_xor_sync(0xffffffffu, rp[i], 1);
        rp[i] += __shfl_xor_sync(0xffffffffu, rp[i], 2);
    }
    // col partials: reduce over lq (8 lanes hold different rows, same col)
#pragma unroll
    for (int nt = 0; nt < 8; nt++) {
        cp0[nt] += __shfl_xor_sync(0xffffffffu, cp0[nt], 4);
        cp0[nt] += __shfl_xor_sync(0xffffffffu, cp0[nt], 8);
        cp0[nt] += __shfl_xor_sync(0xffffffffu, cp0[nt], 16);
        cp1[nt] += __shfl_xor_sync(0xffffffffu, cp1[nt], 4);
        cp1[nt] += __shfl_xor_sync(0xffffffffu, cp1[nt], 8);
        cp1[nt] += __shfl_xor_sync(0xffffffffu, cp1[nt], 16);
    }

    float* s_row = sm;          // [128][2]
    float* s_col = sm + 256;    // [128][4]
    if (lr == 0) {
#pragma unroll
        for (int i = 0; i < 4; i++) {
            int row = wr * 32 + (i >> 1) * 16 + (i & 1) * 8 + lq;
            s_row[row * 2 + wc] = rp[i];
        }
    }
    if (lq == 0) {
#pragma unroll
        for (int nt = 0; nt < 8; nt++) {
            int col = wc * 64 + nt * 8 + 2 * lr;
            s_col[col * 4 + wr] = cp0[nt];
            s_col[(col + 1) * 4 + wr] = cp1[nt];
        }
    }
    __syncthreads();
    if (tid < 128) {
        float z = s_row[tid * 2] + s_row[tid * 2 + 1];
        g_rpart[((size_t)pn * 16 + tj) * SEQ + ti * 128 + tid] = z;
    } else if (ti != tj) {
        int cc = tid - 128;
        float z = s_col[cc * 4] + s_col[cc * 4 + 1] + s_col[cc * 4 + 2] + s_col[cc * 4 + 3];
        g_rpart[((size_t)pn * 16 + ti) * SEQ + tj * 128 + cc] = z;
    }
}

// ---------------------------------------------------------------------------
// Z-reduction: rinv = 1/(sum of 16 tile partials, fixed order);
// diag softmax value = dexp * rinv. grid 128, block 256.
// ---------------------------------------------------------------------------
__global__ __launch_bounds__(256) void zred_kernel()
{
    const int rid = blockIdx.x * 256 + threadIdx.x;   // 0 .. 32767
    const int pn = rid >> 11;
    const int l = rid & (SEQ - 1);
    float z = 0.f;
#pragma unroll
    for (int s = 0; s < 16; s++)
        z += g_rpart[((size_t)pn * 16 + s) * SEQ + l];
    const float inv = 1.f / z;
    g_rinv[rid] = inv;
    g_diag[rid] = g_dexp[rid] * inv;
}

// ---------------------------------------------------------------------------
// Column sums of E * rinv (multiply-only; exp already applied).
// grid (8, 16, 8), block 256.
// ---------------------------------------------------------------------------
__global__ __launch_bounds__(256) void colsum_kernel()
{
    const int col = blockIdx.x * 256 + threadIdx.x;
    const int pn = blockIdx.y;
    const int lc = blockIdx.z;
    const float* __restrict__ att = g_att + (size_t)pn * SEQ * SEQ;
    const float* __restrict__ rinv = g_rinv + pn * SEQ;
    __shared__ float sinv[LCHUNK];
    const int l0 = lc * LCHUNK;
    sinv[threadIdx.x] = rinv[l0 + threadIdx.x];
    __syncthreads();
    const float* base = att + (size_t)l0 * SEQ + col;
    float acc = 0.f;
#pragma unroll 8
    for (int l = 0; l < LCHUNK; l++)
        acc += base[(size_t)l * SEQ] * sinv[l];
    g_part[((size_t)lc * NPAIR * NBATCH + pn) * SEQ + col] = acc;
}

// ---------------------------------------------------------------------------
// Per (pair,batch): final score, bitonic sort, theta = 1024-th smallest.
// ---------------------------------------------------------------------------
__global__ __launch_bounds__(1024) void select_kernel()
{
    const int pn = blockIdx.x;
    __shared__ float s[2048];
    const int tid = threadIdx.x;
    const int PN = NPAIR * NBATCH;
    for (int i = tid; i < SEQ; i += 1024) {
        float v = 0.f;
#pragma unroll
        for (int c = 0; c < LCHUNKS; c++)
            v += g_part[((size_t)c * PN + pn) * SEQ + i];
        v -= g_diag[pn * SEQ + i];
        g_score[pn * SEQ + i] = v;
        s[i] = v;
    }
    __syncthreads();
    for (int k = 2; k <= 2048; k <<= 1) {
        for (int j = k >> 1; j > 0; j >>= 1) {
            for (int idx = tid; idx < 2048; idx += 1024) {
                int ixj = idx ^ j;
                if (ixj > idx) {
                    bool up = ((idx & k) == 0);
                    float a = s[idx], b = s[ixj];
                    if ((a > b) == up) { s[idx] = b; s[ixj] = a; }
                }
            }
            __syncthreads();
        }
    }
    if (tid == 0) g_theta[pn] = s[1023];   // 1024-th smallest
}

// ---------------------------------------------------------------------------
// Output blend.
// ---------------------------------------------------------------------------
__global__ __launch_bounds__(256) void output_kernel(
    const float* __restrict__ xt, const float* __restrict__ xf, float* __restrict__ out)
{
    const int idx = blockIdx.x * 256 + threadIdx.x;
    const int nl = idx >> 5;
    const int n = nl >> 11;
    const int l = nl & (SEQ - 1);
    const float st = g_score[n * SEQ + l];
    const float sf = g_score[(NBATCH + n) * SEQ + l];
    const bool mt = st <= g_theta[n];
    const bool mf = sf <= g_theta[NBATCH + n];
    const bool mt1 = mt && !mf;
    const bool mf1 = mf && !mt;
    const float4 vt = ((const float4*)xt)[idx];
    const float4 vf = ((const float4*)xf)[idx];
    float4 avg;
    avg.x = 0.5f * (vt.x + vf.x);
    avg.y = 0.5f * (vt.y + vf.y);
    avg.z = 0.5f * (vt.z + vf.z);
    avg.w = 0.5f * (vt.w + vf.w);
    ((float4*)out)[idx] = mt1 ? avg : vt;
    ((float4*)out)[(size_t)NBATCH * SEQ * (DIM / 4) + idx] = mf1 ? avg : vf;
}

extern "C" void kernel_launch(void* const* d_in, const int* in_sizes, int n_in,
                              void* d_out, int out_size)
{
    const float* xt = (const float*)d_in[0];
    const float* xf = (const float*)d_in[1];
    const float* W  = (const float*)d_in[2];
    const float* b  = (const float*)d_in[3];
    float* out = (float*)d_out;

    cudaFuncSetAttribute(att_kernel, cudaFuncAttributeMaxDynamicSharedMemorySize,
                         ATT_SMEM);

    proj_kernel<<<dim3(128, 2), 256>>>(xt, xf, W, b);
    att_kernel<<<dim3(136, 8, 2), 256, ATT_SMEM>>>();
    zred_kernel<<<128, 256>>>();
    colsum_kernel<<<dim3(8, 16, LCHUNKS), 256>>>();
    select_kernel<<<16, 1024>>>();
    output_kernel<<<2048, 256>>>(xt, xf, out);
}